// round 12
// baseline (speedup 1.0000x reference)
#include <cuda_runtime.h>

// out[t][l][d]: l==0 -> inputs[t][d], else memory[l][d]
// T=2048, L=64, D=1024 fp32. Pure store-bandwidth kernel (512 MiB writes,
// ~7.3 TB/s effective = ~91% of HBM spec).
//
// Sweep history (256-thr blocks): U=8 75.0us / U=4 74.2 / U=2 73.9 / U=1 74.5.
// This round: 512-thread block covering 2 rows -> per-thread MLP_p1=1
// (cross-CTA L1tex spread floor) at the SAME 65536-block count as the U=2
// winner, isolating MLP from block-churn. .cs streaming stores throughout.

static constexpr int T = 2048;
static constexpr int L = 64;
static constexpr int D4 = 1024 / 4;            // 256 float4 per row
static constexpr int ROWS = T * L;             // 131072
static constexpr int RPB = 2;                  // rows per block (512 threads)

__global__ __launch_bounds__(512, 4)
void sliding_window_memory_kernel(const float4* __restrict__ in,
                                  const float4* __restrict__ mem,
                                  float4* __restrict__ out)
{
    const int tid = threadIdx.x;               // 0..511
    const int d4  = tid & (D4 - 1);            // 0..255
    const int rsub = tid >> 8;                 // 0..1
    const int row = blockIdx.x * RPB + rsub;

    const int l = row & (L - 1);
    const int t = row >> 6;

    const float4* __restrict__ s =
        (l == 0) ? (in + t * D4 + d4) : (mem + l * D4 + d4);

    __stcs(out + (long)row * D4 + d4, __ldg(s));
}

extern "C" void kernel_launch(void* const* d_in, const int* in_sizes, int n_in,
                              void* d_out, int out_size)
{
    const float4* in  = (const float4*)d_in[0];   // inputs [T, D] fp32
    const float4* mem = (const float4*)d_in[1];   // memory [L, D] fp32
    float4* out = (float4*)d_out;                 // [T, L, D] fp32

    sliding_window_memory_kernel<<<ROWS / RPB, 512>>>(in, mem, out);
}

// round 13
// speedup vs baseline: 1.0004x; 1.0004x over previous
#include <cuda_runtime.h>

// out[t][l][d]: l==0 -> inputs[t][d], else memory[l][d]
// T=2048, L=64, D=1024 fp32. Pure store-bandwidth kernel (512 MiB writes,
// ~7.3 TB/s effective = ~91% of HBM spec).
//
// Champion shape (R10): U=2 rows/block, 256 threads, 65536 blocks, .cs
// streaming stores. This round interleaves ld/st pairs (ld0,st0,ld1,st1)
// instead of batching loads -> front-batched LDG count MLP_p1 = 1 (spread
// floor) at the SAME grid/block shape, isolating the last spread term.
// Sweep: U=8 75.0 / U=4 74.2 / U=2-batched 73.9 / U=1 74.5 / 512thr 74.6.

static constexpr int T = 2048;
static constexpr int L = 64;
static constexpr int D4 = 1024 / 4;            // 256 float4 per row
static constexpr int ROWS = T * L;             // 131072
static constexpr int U = 2;                    // rows per block

__device__ __forceinline__ const float4* src_ptr(int row, int tid,
                                                 const float4* __restrict__ in,
                                                 const float4* __restrict__ mem)
{
    const int l = row & (L - 1);
    const int t = row >> 6;
    return (l == 0) ? (in + t * D4 + tid) : (mem + l * D4 + tid);
}

__global__ __launch_bounds__(256, 8)
void sliding_window_memory_kernel(const float4* __restrict__ in,
                                  const float4* __restrict__ mem,
                                  float4* __restrict__ out)
{
    const int tid = threadIdx.x;
    const int row0 = blockIdx.x * U;

    float4* __restrict__ o = out + (long)row0 * D4 + tid;

    // interleaved: store row u before loading row u+1 (MLP_p1 = 1)
    float4 v0 = __ldg(src_ptr(row0 + 0, tid, in, mem));
    __stcs(o, v0);
    float4 v1 = __ldg(src_ptr(row0 + 1, tid, in, mem));
    __stcs(o + D4, v1);
}

extern "C" void kernel_launch(void* const* d_in, const int* in_sizes, int n_in,
                              void* d_out, int out_size)
{
    const float4* in  = (const float4*)d_in[0];   // inputs [T, D] fp32
    const float4* mem = (const float4*)d_in[1];   // memory [L, D] fp32
    float4* out = (float4*)d_out;                 // [T, L, D] fp32

    const int threads = 256;
    const int blocks = ROWS / U;                  // 65536
    sliding_window_memory_kernel<<<blocks, threads>>>(in, mem, out);
}